// round 2
// baseline (speedup 1.0000x reference)
#include <cuda_runtime.h>
#include <cstdint>
#include <cstddef>

// ============================================================================
//   z[8192,32] = relu( Gi2j@(xi Wi+bi) + Adj2j@(xj1 Wj1+bj1)
//                    + coAdj2j@(xj1 Wj2+bj2) + Gk2j@(xk Wk+bk) )
// Inputs (metadata order):
//   0 xi, 1 xj1, 2 xj2(unused), 3 xk, 4 Gi2j, 5 Adj2j, 6 coAdj2j, 7 Gk2j,
//   8..11 W_i,W_j1,W_j2,W_k, 12..15 b_i,b_j1,b_j2,b_k
//
// Strategy: the bench's PTX target is plain sm_103 (no 'a' features), so no
// tcgen05/TMEM. Use baseline mma.sync.m16n8k8.tf32 (HMMA path) with a 4-stage
// cp.async pipeline. HBM floor ~140us for the 1.07GB of G reads.
// ============================================================================

// Scratch (allocation-free: __device__ globals)
__device__ float g_B[4 * 32 * 8192];        // [branch][c][k]  (Y_m^T, k-contiguous)
__device__ float g_partial[4 * 8192 * 32];  // [branch][j][c]

__device__ __forceinline__ uint32_t smem_u32(const void* p) {
    uint32_t a;
    asm("{ .reg .u64 t; cvta.to.shared.u64 t, %1; cvt.u32.u64 %0, t; }" : "=r"(a) : "l"(p));
    return a;
}

#define CP_ASYNC16(dst, src) \
    asm volatile("cp.async.cg.shared.global [%0], [%1], 16;" :: "r"(dst), "l"(src) : "memory")
#define CP_COMMIT() asm volatile("cp.async.commit_group;" ::: "memory")
#define CP_WAIT2()  asm volatile("cp.async.wait_group 2;" ::: "memory")

// Load fp32 from smem and round to tf32 (rna) in-register.
__device__ __forceinline__ uint32_t lds_tf32(uint32_t addr) {
    uint32_t v;
    asm volatile("ld.shared.b32 %0, [%1];" : "=r"(v) : "r"(addr));
    asm volatile("cvt.rna.tf32.f32 %0, %0;" : "+r"(v));
    return v;
}

__device__ __forceinline__ void mma_tf32(float& c0, float& c1, float& c2, float& c3,
                                         uint32_t a0, uint32_t a1, uint32_t a2, uint32_t a3,
                                         uint32_t b0, uint32_t b1) {
    asm volatile(
        "mma.sync.aligned.m16n8k8.row.col.f32.tf32.tf32.f32 "
        "{%0,%1,%2,%3}, {%4,%5,%6,%7}, {%8,%9}, {%0,%1,%2,%3};"
        : "+f"(c0), "+f"(c1), "+f"(c2), "+f"(c3)
        : "r"(a0), "r"(a1), "r"(a2), "r"(a3), "r"(b0), "r"(b1));
}

// ============================================================================
// Kernel 1: B prep  —  g_B[m][c][k] = b_m[c] + sum_t x_m[k,t] * W_m[t,c]
// ============================================================================
__global__ void prep_kernel(
    const float* __restrict__ xi, const float* __restrict__ xj1, const float* __restrict__ xk,
    const float* __restrict__ Wi, const float* __restrict__ Wj1,
    const float* __restrict__ Wj2, const float* __restrict__ Wk,
    const float* __restrict__ bi, const float* __restrict__ bj1,
    const float* __restrict__ bj2, const float* __restrict__ bk)
{
    const int m = blockIdx.y;
    const float* x = (m == 0) ? xi : (m == 3) ? xk : xj1;  // branch 2 uses xj1 (faithful)
    const float* W = (m == 0) ? Wi : (m == 1) ? Wj1 : (m == 2) ? Wj2 : Wk;
    const float* b = (m == 0) ? bi : (m == 1) ? bj1 : (m == 2) ? bj2 : bk;

    __shared__ float Ws[32][32];
    __shared__ float bs[32];
    const int tid = threadIdx.x;
    for (int i = tid; i < 1024; i += 256) Ws[i >> 5][i & 31] = W[i];
    if (tid < 32) bs[tid] = b[tid];
    __syncthreads();

    const int k = blockIdx.x * 256 + tid;
    float xr[32];
    const float4* xrow = reinterpret_cast<const float4*>(x + (size_t)k * 32);
#pragma unroll
    for (int t = 0; t < 8; t++) {
        float4 v = xrow[t];
        xr[4 * t] = v.x; xr[4 * t + 1] = v.y; xr[4 * t + 2] = v.z; xr[4 * t + 3] = v.w;
    }
    float* Bout = g_B + (size_t)m * 32 * 8192;
#pragma unroll 4
    for (int c = 0; c < 32; c++) {
        float acc = bs[c];
#pragma unroll
        for (int t = 0; t < 32; t++) acc += xr[t] * Ws[t][c];
        Bout[(size_t)c * 8192 + k] = acc;  // coalesced across k
    }
}

// ============================================================================
// Kernel 2: tf32 mma.sync GEMM — partial[m][jtile] = G_m[jtile,:] @ Y_m
//   grid (64 M-tiles, 4 branches), 128 threads (4 warps, each owns 32 rows).
//   K streamed in 256 chunks of 32 floats. 4-stage cp.async ring.
//   Smem rows padded to 36 floats (144B) -> conflict-free fragment LDS.
// ============================================================================
#define S_STAGES 4
#define T_CHUNKS 256                 // 8192 / 32
#define ROW_B 144                    // 36 floats, 16B aligned
#define A_BYTES (128 * ROW_B)        // 18432
#define B_OFF   A_BYTES
#define STAGE_BYTES (A_BYTES + 32 * ROW_B)   // 23040
#define SMEM_TOTAL (S_STAGES * STAGE_BYTES)  // 92160

__device__ __forceinline__ void load_stage(uint32_t sbase, const float* __restrict__ G,
                                           const float* __restrict__ B, int slot, int kchunk,
                                           int mtile, int tid)
{
    const int kbase = kchunk * 32;
    const uint32_t st = sbase + slot * STAGE_BYTES;
    // A: 128 rows x 8 chunks of 16B (8 consecutive threads -> 128B coalesced)
#pragma unroll
    for (int i = 0; i < 8; i++) {
        int ch = tid + i * 128;              // 0..1023
        int r = ch >> 3, q = ch & 7;
        uint32_t dst = st + r * ROW_B + q * 16;
        const float* src = G + (size_t)(mtile * 128 + r) * 8192 + kbase + q * 4;
        CP_ASYNC16(dst, src);
    }
    // B: 32 rows x 8 chunks of 16B
#pragma unroll
    for (int i = 0; i < 2; i++) {
        int ch = tid + i * 128;              // 0..255
        int r = ch >> 3, q = ch & 7;
        uint32_t dst = st + B_OFF + r * ROW_B + q * 16;
        const float* src = B + (size_t)r * 8192 + kbase + q * 4;
        CP_ASYNC16(dst, src);
    }
}

__global__ void __launch_bounds__(128)
gemm_tf32_kernel(const float* __restrict__ G0, const float* __restrict__ G1,
                 const float* __restrict__ G2, const float* __restrict__ G3)
{
    extern __shared__ __align__(128) char smem[];
    const uint32_t sbase = smem_u32(smem);
    const int tid = threadIdx.x;
    const int w = tid >> 5;
    const int lid = tid & 31;
    const int l4 = lid >> 2;       // 0..7
    const int lm = lid & 3;        // 0..3
    const int mtile = blockIdx.x;
    const int branch = blockIdx.y;
    const float* __restrict__ G =
        (branch == 0) ? G0 : (branch == 1) ? G1 : (branch == 2) ? G2 : G3;
    const float* __restrict__ B = g_B + (size_t)branch * 32 * 8192;

    float acc[2][4][4];            // [mtile16][ntile8][frag]
#pragma unroll
    for (int a = 0; a < 2; a++)
#pragma unroll
        for (int b = 0; b < 4; b++)
#pragma unroll
            for (int c = 0; c < 4; c++) acc[a][b][c] = 0.0f;

    // Prologue: fill stages 0..2
    for (int s = 0; s < S_STAGES - 1; s++) {
        load_stage(sbase, G, B, s, s, mtile, tid);
        CP_COMMIT();
    }

    for (int t = 0; t < T_CHUNKS; t++) {
        CP_WAIT2();                // stage t complete (<=2 groups pending)
        __syncthreads();           // all warps done reading slot (t-1)%4 too

        const int lk = t + S_STAGES - 1;
        if (lk < T_CHUNKS) load_stage(sbase, G, B, lk & 3, lk, mtile, tid);
        CP_COMMIT();               // commit every iter (possibly empty group)

        const uint32_t st = sbase + (t & 3) * STAGE_BYTES;
        // Per-thread fragment bases (conflict-free: bank = (4r + c) mod 32)
        const uint32_t a_base = st + (w * 32 + l4) * ROW_B + lm * 4;
        const uint32_t b_base = st + B_OFF + l4 * ROW_B + lm * 4;

#pragma unroll
        for (int k0 = 0; k0 < 4; k0++) {   // 4 k-steps of 8
            const uint32_t ka = a_base + k0 * 32;   // +8 floats
            const uint32_t kb = b_base + k0 * 32;

            uint32_t bf[4][2];
#pragma unroll
            for (int nt = 0; nt < 4; nt++) {
                bf[nt][0] = lds_tf32(kb + nt * (8 * ROW_B));
                bf[nt][1] = lds_tf32(kb + nt * (8 * ROW_B) + 16);
            }
#pragma unroll
            for (int mt = 0; mt < 2; mt++) {
                const uint32_t am = ka + mt * (16 * ROW_B);
                uint32_t a0 = lds_tf32(am);
                uint32_t a1 = lds_tf32(am + 8 * ROW_B);
                uint32_t a2 = lds_tf32(am + 16);
                uint32_t a3 = lds_tf32(am + 8 * ROW_B + 16);
#pragma unroll
                for (int nt = 0; nt < 4; nt++)
                    mma_tf32(acc[mt][nt][0], acc[mt][nt][1], acc[mt][nt][2], acc[mt][nt][3],
                             a0, a1, a2, a3, bf[nt][0], bf[nt][1]);
            }
        }
    }

    // Epilogue: c-frag layout m16n8: thread holds rows l4, l4+8; cols 2*lm, 2*lm+1
    float* P = g_partial + (size_t)branch * 8192 * 32;
#pragma unroll
    for (int mt = 0; mt < 2; mt++) {
        const int r0 = mtile * 128 + w * 32 + mt * 16 + l4;
#pragma unroll
        for (int nt = 0; nt < 4; nt++) {
            const int col = nt * 8 + lm * 2;
            float2* d0 = reinterpret_cast<float2*>(P + (size_t)r0 * 32 + col);
            float2* d1 = reinterpret_cast<float2*>(P + (size_t)(r0 + 8) * 32 + col);
            *d0 = make_float2(acc[mt][nt][0], acc[mt][nt][1]);
            *d1 = make_float2(acc[mt][nt][2], acc[mt][nt][3]);
        }
    }
}

// ============================================================================
// Kernel 3: reduce 4 partials + relu -> out[8192,32] f32
// ============================================================================
__global__ void reduce_relu_kernel(float4* __restrict__ out)
{
    const int i = blockIdx.x * blockDim.x + threadIdx.x;     // 0..65535 float4s
    const float4* p = reinterpret_cast<const float4*>(g_partial);
    float4 a = p[i], b = p[i + 65536], c = p[i + 131072], d = p[i + 196608];
    float4 r;
    r.x = fmaxf(a.x + b.x + c.x + d.x, 0.0f);
    r.y = fmaxf(a.y + b.y + c.y + d.y, 0.0f);
    r.z = fmaxf(a.z + b.z + c.z + d.z, 0.0f);
    r.w = fmaxf(a.w + b.w + c.w + d.w, 0.0f);
    out[i] = r;
}

// ============================================================================
// Launch
// ============================================================================
extern "C" void kernel_launch(void* const* d_in, const int* in_sizes, int n_in,
                              void* d_out, int out_size)
{
    const float* xi  = (const float*)d_in[0];
    const float* xj1 = (const float*)d_in[1];
    const float* xk  = (const float*)d_in[3];
    const float* Gi  = (const float*)d_in[4];
    const float* Ad  = (const float*)d_in[5];
    const float* co  = (const float*)d_in[6];
    const float* Gk  = (const float*)d_in[7];

    cudaFuncSetAttribute(gemm_tf32_kernel,
                         cudaFuncAttributeMaxDynamicSharedMemorySize, SMEM_TOTAL);

    prep_kernel<<<dim3(32, 4), 256>>>(
        xi, xj1, xk,
        (const float*)d_in[8],  (const float*)d_in[9],
        (const float*)d_in[10], (const float*)d_in[11],
        (const float*)d_in[12], (const float*)d_in[13],
        (const float*)d_in[14], (const float*)d_in[15]);

    gemm_tf32_kernel<<<dim3(64, 4), 128, SMEM_TOTAL>>>(Gi, Ad, co, Gk);

    reduce_relu_kernel<<<256, 256>>>((float4*)d_out);
}

// round 3
// speedup vs baseline: 1.0339x; 1.0339x over previous
#include <cuda_runtime.h>
#include <cstdint>
#include <cstddef>

// ============================================================================
//   z[8192,32] = relu( Gi2j@(xi Wi+bi) + Adj2j@(xj1 Wj1+bj1)
//                    + coAdj2j@(xj1 Wj2+bj2) + Gk2j@(xk Wk+bk) )
// Inputs (metadata order):
//   0 xi, 1 xj1, 2 xj2(unused), 3 xk, 4 Gi2j, 5 Adj2j, 6 coAdj2j, 7 Gk2j,
//   8..11 W_i,W_j1,W_j2,W_k, 12..15 b_i,b_j1,b_j2,b_k
//
// Bench PTX target is plain sm_103 (no 'a' features): no tcgen05/TMEM.
// Baseline mma.sync.m16n8k8.tf32 + 5-stage cp.async pipeline.
// R3: 5 stages / wait_group 3 (deeper in-flight), pinned 2 CTAs/SM, fast prep.
// ============================================================================

// Scratch (allocation-free: __device__ globals)
__device__ float g_B[4 * 32 * 8192];        // [branch][c][k]  (Y_m^T, k-contiguous)
__device__ float g_partial[4 * 8192 * 32];  // [branch][j][c]

__device__ __forceinline__ uint32_t smem_u32(const void* p) {
    uint32_t a;
    asm("{ .reg .u64 t; cvta.to.shared.u64 t, %1; cvt.u32.u64 %0, t; }" : "=r"(a) : "l"(p));
    return a;
}

#define CP_ASYNC16(dst, src) \
    asm volatile("cp.async.cg.shared.global [%0], [%1], 16;" :: "r"(dst), "l"(src) : "memory")
#define CP_COMMIT() asm volatile("cp.async.commit_group;" ::: "memory")
#define CP_WAIT3()  asm volatile("cp.async.wait_group 3;" ::: "memory")

// Load fp32 from smem and round to tf32 (rna) in-register.
__device__ __forceinline__ uint32_t lds_tf32(uint32_t addr) {
    uint32_t v;
    asm volatile("ld.shared.b32 %0, [%1];" : "=r"(v) : "r"(addr));
    asm volatile("cvt.rna.tf32.f32 %0, %0;" : "+r"(v));
    return v;
}

__device__ __forceinline__ void mma_tf32(float& c0, float& c1, float& c2, float& c3,
                                         uint32_t a0, uint32_t a1, uint32_t a2, uint32_t a3,
                                         uint32_t b0, uint32_t b1) {
    asm volatile(
        "mma.sync.aligned.m16n8k8.row.col.f32.tf32.tf32.f32 "
        "{%0,%1,%2,%3}, {%4,%5,%6,%7}, {%8,%9}, {%0,%1,%2,%3};"
        : "+f"(c0), "+f"(c1), "+f"(c2), "+f"(c3)
        : "r"(a0), "r"(a1), "r"(a2), "r"(a3), "r"(b0), "r"(b1));
}

// ============================================================================
// Kernel 1: B prep  —  g_B[m][c][k] = b_m[c] + sum_t x_m[k,t] * W_m[t,c]
//   block = 256 threads = {cq 0..3} x {kloc 0..63}; each thread does 8 c's.
//   grid (128, 4). Consecutive tids share cq -> coalesced k stores.
// ============================================================================
__global__ void __launch_bounds__(256) prep_kernel(
    const float* __restrict__ xi, const float* __restrict__ xj1, const float* __restrict__ xk,
    const float* __restrict__ Wi, const float* __restrict__ Wj1,
    const float* __restrict__ Wj2, const float* __restrict__ Wk,
    const float* __restrict__ bi, const float* __restrict__ bj1,
    const float* __restrict__ bj2, const float* __restrict__ bk)
{
    const int m = blockIdx.y;
    const float* x = (m == 0) ? xi : (m == 3) ? xk : xj1;  // branch 2 uses xj1 (faithful)
    const float* W = (m == 0) ? Wi : (m == 1) ? Wj1 : (m == 2) ? Wj2 : Wk;
    const float* b = (m == 0) ? bi : (m == 1) ? bj1 : (m == 2) ? bj2 : bk;

    __shared__ float Ws[32][32];
    __shared__ float bs[32];
    const int tid = threadIdx.x;
    for (int i = tid; i < 1024; i += 256) Ws[i >> 5][i & 31] = W[i];
    if (tid < 32) bs[tid] = b[tid];
    __syncthreads();

    const int cq = tid >> 6;                 // 0..3  -> c block of 8
    const int kloc = tid & 63;               // 0..63
    const int k = blockIdx.x * 64 + kloc;

    float xr[32];
    const float4* xrow = reinterpret_cast<const float4*>(x + (size_t)k * 32);
#pragma unroll
    for (int t = 0; t < 8; t++) {
        float4 v = xrow[t];
        xr[4 * t] = v.x; xr[4 * t + 1] = v.y; xr[4 * t + 2] = v.z; xr[4 * t + 3] = v.w;
    }
    float acc[8];
#pragma unroll
    for (int c8 = 0; c8 < 8; c8++) acc[c8] = bs[cq * 8 + c8];
#pragma unroll
    for (int t = 0; t < 32; t++) {
        const float xv = xr[t];
#pragma unroll
        for (int c8 = 0; c8 < 8; c8++) acc[c8] += xv * Ws[t][cq * 8 + c8];
    }
    float* Bout = g_B + (size_t)m * 32 * 8192;
#pragma unroll
    for (int c8 = 0; c8 < 8; c8++)
        Bout[(size_t)(cq * 8 + c8) * 8192 + k] = acc[c8];   // 64 consecutive k / write
}

// ============================================================================
// Kernel 2: tf32 mma.sync GEMM — partial[m][jtile] = G_m[jtile,:] @ Y_m
//   grid (64 M-tiles, 4 branches), 128 threads (4 warps, each owns 32 rows).
//   K streamed in 256 chunks of 32 floats. 5-stage cp.async ring, wait_group 3.
//   Smem rows padded to 36 floats (144B) -> conflict-free fragment LDS.
// ============================================================================
#define S_STAGES 5
#define T_CHUNKS 256                 // 8192 / 32
#define ROW_B 144                    // 36 floats, 16B aligned
#define A_BYTES (128 * ROW_B)        // 18432
#define B_OFF   A_BYTES
#define STAGE_BYTES (A_BYTES + 32 * ROW_B)   // 23040
#define SMEM_TOTAL (S_STAGES * STAGE_BYTES)  // 115200 (112.5 KB; 2 CTA/SM = 225 KB)

__device__ __forceinline__ void load_stage(uint32_t sbase, const float* __restrict__ G,
                                           const float* __restrict__ B, int slot, int kchunk,
                                           int mtile, int tid)
{
    const int kbase = kchunk * 32;
    const uint32_t st = sbase + slot * STAGE_BYTES;
    // A: 128 rows x 8 chunks of 16B (8 consecutive threads -> 128B coalesced)
#pragma unroll
    for (int i = 0; i < 8; i++) {
        int ch = tid + i * 128;              // 0..1023
        int r = ch >> 3, q = ch & 7;
        uint32_t dst = st + r * ROW_B + q * 16;
        const float* src = G + (size_t)(mtile * 128 + r) * 8192 + kbase + q * 4;
        CP_ASYNC16(dst, src);
    }
    // B: 32 rows x 8 chunks of 16B
#pragma unroll
    for (int i = 0; i < 2; i++) {
        int ch = tid + i * 128;              // 0..255
        int r = ch >> 3, q = ch & 7;
        uint32_t dst = st + B_OFF + r * ROW_B + q * 16;
        const float* src = B + (size_t)r * 8192 + kbase + q * 4;
        CP_ASYNC16(dst, src);
    }
}

__global__ void __launch_bounds__(128, 2)
gemm_tf32_kernel(const float* __restrict__ G0, const float* __restrict__ G1,
                 const float* __restrict__ G2, const float* __restrict__ G3)
{
    extern __shared__ __align__(128) char smem[];
    const uint32_t sbase = smem_u32(smem);
    const int tid = threadIdx.x;
    const int w = tid >> 5;
    const int lid = tid & 31;
    const int l4 = lid >> 2;       // 0..7
    const int lm = lid & 3;        // 0..3
    const int mtile = blockIdx.x;
    const int branch = blockIdx.y;
    const float* __restrict__ G =
        (branch == 0) ? G0 : (branch == 1) ? G1 : (branch == 2) ? G2 : G3;
    const float* __restrict__ B = g_B + (size_t)branch * 32 * 8192;

    float acc[2][4][4];            // [mtile16][ntile8][frag]
#pragma unroll
    for (int a = 0; a < 2; a++)
#pragma unroll
        for (int b = 0; b < 4; b++)
#pragma unroll
            for (int c = 0; c < 4; c++) acc[a][b][c] = 0.0f;

    // Prologue: fill stages 0..3 (4 committed groups in flight)
    for (int s = 0; s < S_STAGES - 1; s++) {
        load_stage(sbase, G, B, s, s, mtile, tid);
        CP_COMMIT();
    }

    int slot = 0;                  // = t % 5
    int lslot = S_STAGES - 1;      // = (t+4) % 5
    for (int t = 0; t < T_CHUNKS; t++) {
        CP_WAIT3();                // chunk t complete (3 newer groups may pend)
        __syncthreads();           // all warps done reading slot being refilled

        const int lk = t + S_STAGES - 1;
        if (lk < T_CHUNKS) load_stage(sbase, G, B, lslot, lk, mtile, tid);
        CP_COMMIT();               // commit every iter (possibly empty group)

        const uint32_t st = sbase + slot * STAGE_BYTES;
        // Per-thread fragment bases (conflict-free: bank = (4*l4 + lm) mod 32)
        const uint32_t a_base = st + (w * 32 + l4) * ROW_B + lm * 4;
        const uint32_t b_base = st + B_OFF + l4 * ROW_B + lm * 4;

#pragma unroll
        for (int k0 = 0; k0 < 4; k0++) {   // 4 k-steps of 8
            const uint32_t ka = a_base + k0 * 32;   // +8 floats
            const uint32_t kb = b_base + k0 * 32;

            uint32_t bf[4][2];
#pragma unroll
            for (int nt = 0; nt < 4; nt++) {
                bf[nt][0] = lds_tf32(kb + nt * (8 * ROW_B));
                bf[nt][1] = lds_tf32(kb + nt * (8 * ROW_B) + 16);
            }
#pragma unroll
            for (int mt = 0; mt < 2; mt++) {
                const uint32_t am = ka + mt * (16 * ROW_B);
                uint32_t a0 = lds_tf32(am);
                uint32_t a1 = lds_tf32(am + 8 * ROW_B);
                uint32_t a2 = lds_tf32(am + 16);
                uint32_t a3 = lds_tf32(am + 8 * ROW_B + 16);
#pragma unroll
                for (int nt = 0; nt < 4; nt++)
                    mma_tf32(acc[mt][nt][0], acc[mt][nt][1], acc[mt][nt][2], acc[mt][nt][3],
                             a0, a1, a2, a3, bf[nt][0], bf[nt][1]);
            }
        }
        slot = (slot == S_STAGES - 1) ? 0 : slot + 1;
        lslot = (lslot == S_STAGES - 1) ? 0 : lslot + 1;
    }

    // Epilogue: c-frag m16n8: thread holds rows l4, l4+8; cols 2*lm, 2*lm+1
    float* P = g_partial + (size_t)branch * 8192 * 32;
#pragma unroll
    for (int mt = 0; mt < 2; mt++) {
        const int r0 = mtile * 128 + w * 32 + mt * 16 + l4;
#pragma unroll
        for (int nt = 0; nt < 4; nt++) {
            const int col = nt * 8 + lm * 2;
            float2* d0 = reinterpret_cast<float2*>(P + (size_t)r0 * 32 + col);
            float2* d1 = reinterpret_cast<float2*>(P + (size_t)(r0 + 8) * 32 + col);
            *d0 = make_float2(acc[mt][nt][0], acc[mt][nt][1]);
            *d1 = make_float2(acc[mt][nt][2], acc[mt][nt][3]);
        }
    }
}

// ============================================================================
// Kernel 3: reduce 4 partials + relu -> out[8192,32] f32
// ============================================================================
__global__ void reduce_relu_kernel(float4* __restrict__ out)
{
    const int i = blockIdx.x * blockDim.x + threadIdx.x;     // 0..65535 float4s
    const float4* p = reinterpret_cast<const float4*>(g_partial);
    float4 a = p[i], b = p[i + 65536], c = p[i + 131072], d = p[i + 196608];
    float4 r;
    r.x = fmaxf(a.x + b.x + c.x + d.x, 0.0f);
    r.y = fmaxf(a.y + b.y + c.y + d.y, 0.0f);
    r.z = fmaxf(a.z + b.z + c.z + d.z, 0.0f);
    r.w = fmaxf(a.w + b.w + c.w + d.w, 0.0f);
    out[i] = r;
}

// ============================================================================
// Launch
// ============================================================================
extern "C" void kernel_launch(void* const* d_in, const int* in_sizes, int n_in,
                              void* d_out, int out_size)
{
    const float* xi  = (const float*)d_in[0];
    const float* xj1 = (const float*)d_in[1];
    const float* xk  = (const float*)d_in[3];
    const float* Gi  = (const float*)d_in[4];
    const float* Ad  = (const float*)d_in[5];
    const float* co  = (const float*)d_in[6];
    const float* Gk  = (const float*)d_in[7];

    cudaFuncSetAttribute(gemm_tf32_kernel,
                         cudaFuncAttributeMaxDynamicSharedMemorySize, SMEM_TOTAL);
    cudaFuncSetAttribute(gemm_tf32_kernel,
                         cudaFuncAttributePreferredSharedMemoryCarveout, 100);

    prep_kernel<<<dim3(128, 4), 256>>>(
        xi, xj1, xk,
        (const float*)d_in[8],  (const float*)d_in[9],
        (const float*)d_in[10], (const float*)d_in[11],
        (const float*)d_in[12], (const float*)d_in[13],
        (const float*)d_in[14], (const float*)d_in[15]);

    gemm_tf32_kernel<<<dim3(64, 4), 128, SMEM_TOTAL>>>(Gi, Ad, co, Gk);

    reduce_relu_kernel<<<256, 256>>>((float4*)d_out);
}

// round 4
// speedup vs baseline: 1.0545x; 1.0199x over previous
#include <cuda_runtime.h>
#include <cstdint>
#include <cstddef>

// ============================================================================
//   z[8192,32] = relu( Gi2j@(xi Wi+bi) + Adj2j@(xj1 Wj1+bj1)
//                    + coAdj2j@(xj1 Wj2+bj2) + Gk2j@(xk Wk+bk) )
// Inputs (metadata order):
//   0 xi, 1 xj1, 2 xj2(unused), 3 xk, 4 Gi2j, 5 Adj2j, 6 coAdj2j, 7 Gk2j,
//   8..11 W_i,W_j1,W_j2,W_k, 12..15 b_i,b_j1,b_j2,b_k
//
// Bench PTX target is plain sm_103 (no 'a' features): no tcgen05/TMEM.
// Baseline mma.sync.m16n8k8.tf32 + cp.async pipeline.
// R4: M_TILE=256 (halves B L2 traffic), L2::256B prefetch on A, faster prep.
// ============================================================================

// Scratch (allocation-free: __device__ globals)
__device__ float g_B[4 * 32 * 8192];        // [branch][c][k]  (Y_m^T, k-contiguous)
__device__ float g_partial[4 * 8192 * 32];  // [branch][j][c]

__device__ __forceinline__ uint32_t smem_u32(const void* p) {
    uint32_t a;
    asm("{ .reg .u64 t; cvta.to.shared.u64 t, %1; cvt.u32.u64 %0, t; }" : "=r"(a) : "l"(p));
    return a;
}

#define CP_ASYNC16(dst, src) \
    asm volatile("cp.async.cg.shared.global [%0], [%1], 16;" :: "r"(dst), "l"(src) : "memory")
#define CP_ASYNC16_PF(dst, src) \
    asm volatile("cp.async.cg.shared.global.L2::256B [%0], [%1], 16;" :: "r"(dst), "l"(src) : "memory")
#define CP_COMMIT() asm volatile("cp.async.commit_group;" ::: "memory")
#define CP_WAIT2()  asm volatile("cp.async.wait_group 2;" ::: "memory")

// Load fp32 from smem and round to tf32 (rna) in-register.
__device__ __forceinline__ uint32_t lds_tf32(uint32_t addr) {
    uint32_t v;
    asm volatile("ld.shared.b32 %0, [%1];" : "=r"(v) : "r"(addr));
    asm volatile("cvt.rna.tf32.f32 %0, %0;" : "+r"(v));
    return v;
}

__device__ __forceinline__ void mma_tf32(float& c0, float& c1, float& c2, float& c3,
                                         uint32_t a0, uint32_t a1, uint32_t a2, uint32_t a3,
                                         uint32_t b0, uint32_t b1) {
    asm volatile(
        "mma.sync.aligned.m16n8k8.row.col.f32.tf32.tf32.f32 "
        "{%0,%1,%2,%3}, {%4,%5,%6,%7}, {%8,%9}, {%0,%1,%2,%3};"
        : "+f"(c0), "+f"(c1), "+f"(c2), "+f"(c3)
        : "r"(a0), "r"(a1), "r"(a2), "r"(a3), "r"(b0), "r"(b1));
}

// ============================================================================
// Kernel 1: B prep  —  g_B[m][c][k] = b_m[c] + sum_t x_m[k,t] * W_m[t,c]
//   block = 256 threads = {chalf 0..1} x {kloc 0..127}; thread does 16 c's.
//   grid (64, 4). Consecutive tids share chalf -> coalesced k stores.
// ============================================================================
__global__ void __launch_bounds__(256) prep_kernel(
    const float* __restrict__ xi, const float* __restrict__ xj1, const float* __restrict__ xk,
    const float* __restrict__ Wi, const float* __restrict__ Wj1,
    const float* __restrict__ Wj2, const float* __restrict__ Wk,
    const float* __restrict__ bi, const float* __restrict__ bj1,
    const float* __restrict__ bj2, const float* __restrict__ bk)
{
    const int m = blockIdx.y;
    const float* x = (m == 0) ? xi : (m == 3) ? xk : xj1;  // branch 2 uses xj1 (faithful)
    const float* W = (m == 0) ? Wi : (m == 1) ? Wj1 : (m == 2) ? Wj2 : Wk;
    const float* b = (m == 0) ? bi : (m == 1) ? bj1 : (m == 2) ? bj2 : bk;

    __shared__ float Ws[32][32];
    __shared__ float bs[32];
    const int tid = threadIdx.x;
    for (int i = tid; i < 1024; i += 256) Ws[i >> 5][i & 31] = W[i];
    if (tid < 32) bs[tid] = b[tid];
    __syncthreads();

    const int kloc = tid & 127;
    const int c0 = (tid >> 7) * 16;          // 0 or 16
    const int k = blockIdx.x * 128 + kloc;

    float xr[32];
    const float4* xrow = reinterpret_cast<const float4*>(x + (size_t)k * 32);
#pragma unroll
    for (int t = 0; t < 8; t++) {
        float4 v = xrow[t];
        xr[4 * t] = v.x; xr[4 * t + 1] = v.y; xr[4 * t + 2] = v.z; xr[4 * t + 3] = v.w;
    }
    float acc[16];
#pragma unroll
    for (int c = 0; c < 16; c++) acc[c] = bs[c0 + c];
#pragma unroll
    for (int t = 0; t < 32; t++) {
        const float xv = xr[t];
#pragma unroll
        for (int c = 0; c < 16; c++) acc[c] += xv * Ws[t][c0 + c];
    }
    float* Bout = g_B + (size_t)m * 32 * 8192;
#pragma unroll
    for (int c = 0; c < 16; c++)
        Bout[(size_t)(c0 + c) * 8192 + k] = acc[c];   // 128 consecutive k / write
}

// ============================================================================
// Kernel 2: tf32 mma.sync GEMM — partial[m][jtile] = G_m[jtile,:] @ Y_m
//   grid (32 M-tiles, 4 branches) = 128 CTAs, 256 threads (8 warps x 32 rows).
//   M_TILE=256. K streamed in 256 chunks of 32 floats. 4-stage cp.async ring.
//   Smem rows padded to 36 floats (144B) -> conflict-free fragment LDS.
// ============================================================================
#define M_TILE  256
#define S_STAGES 4
#define T_CHUNKS 256                 // 8192 / 32
#define ROW_B 144                    // 36 floats, 16B aligned
#define A_BYTES (M_TILE * ROW_B)     // 36864
#define B_OFF   A_BYTES
#define STAGE_BYTES (A_BYTES + 32 * ROW_B)   // 41472
#define SMEM_TOTAL (S_STAGES * STAGE_BYTES)  // 165888 (162 KB; 1 CTA/SM)

__device__ __forceinline__ void load_stage(uint32_t sbase, const float* __restrict__ G,
                                           const float* __restrict__ B, int slot, int kchunk,
                                           int mtile, int tid)
{
    const int kbase = kchunk * 32;
    const uint32_t st = sbase + slot * STAGE_BYTES;
    // A: 256 rows x 8 chunks of 16B (8 consecutive threads -> 128B coalesced)
#pragma unroll
    for (int i = 0; i < 8; i++) {
        int ch = tid + i * 256;              // 0..2047
        int r = ch >> 3, q = ch & 7;
        uint32_t dst = st + r * ROW_B + q * 16;
        const float* src = G + (size_t)(mtile * M_TILE + r) * 8192 + kbase + q * 4;
        CP_ASYNC16_PF(dst, src);             // L2::256B warms next chunk
    }
    // B: 32 rows x 8 chunks of 16B (one op per thread)
    {
        int r = tid >> 3, q = tid & 7;
        uint32_t dst = st + B_OFF + r * ROW_B + q * 16;
        const float* src = B + (size_t)r * 8192 + kbase + q * 4;
        CP_ASYNC16(dst, src);
    }
}

__global__ void __launch_bounds__(256, 1)
gemm_tf32_kernel(const float* __restrict__ G0, const float* __restrict__ G1,
                 const float* __restrict__ G2, const float* __restrict__ G3)
{
    extern __shared__ __align__(128) char smem[];
    const uint32_t sbase = smem_u32(smem);
    const int tid = threadIdx.x;
    const int w = tid >> 5;        // 0..7 (warp owns rows w*32..w*32+31)
    const int lid = tid & 31;
    const int l4 = lid >> 2;       // 0..7
    const int lm = lid & 3;        // 0..3
    const int mtile = blockIdx.x;
    const int branch = blockIdx.y;
    const float* __restrict__ G =
        (branch == 0) ? G0 : (branch == 1) ? G1 : (branch == 2) ? G2 : G3;
    const float* __restrict__ B = g_B + (size_t)branch * 32 * 8192;

    float acc[2][4][4];            // [mtile16][ntile8][frag]
#pragma unroll
    for (int a = 0; a < 2; a++)
#pragma unroll
        for (int b = 0; b < 4; b++)
#pragma unroll
            for (int c = 0; c < 4; c++) acc[a][b][c] = 0.0f;

    // Prologue: fill stages 0..2 (3 committed groups in flight = 108 KB)
    for (int s = 0; s < S_STAGES - 1; s++) {
        load_stage(sbase, G, B, s, s, mtile, tid);
        CP_COMMIT();
    }

    int slot = 0;                  // = t % 4
    int lslot = S_STAGES - 1;      // = (t+3) % 4
    for (int t = 0; t < T_CHUNKS; t++) {
        CP_WAIT2();                // chunk t complete (2 newer groups may pend)
        __syncthreads();           // all warps done reading slot being refilled

        const int lk = t + S_STAGES - 1;
        if (lk < T_CHUNKS) load_stage(sbase, G, B, lslot, lk, mtile, tid);
        CP_COMMIT();               // commit every iter (possibly empty group)

        const uint32_t st = sbase + slot * STAGE_BYTES;
        // Per-thread fragment bases (conflict-free: bank = (4*l4 + lm) mod 32)
        const uint32_t a_base = st + (w * 32 + l4) * ROW_B + lm * 4;
        const uint32_t b_base = st + B_OFF + l4 * ROW_B + lm * 4;

#pragma unroll
        for (int k0 = 0; k0 < 4; k0++) {   // 4 k-steps of 8
            const uint32_t ka = a_base + k0 * 32;   // +8 floats
            const uint32_t kb = b_base + k0 * 32;

            uint32_t bf[4][2];
#pragma unroll
            for (int nt = 0; nt < 4; nt++) {
                bf[nt][0] = lds_tf32(kb + nt * (8 * ROW_B));
                bf[nt][1] = lds_tf32(kb + nt * (8 * ROW_B) + 16);
            }
#pragma unroll
            for (int mt = 0; mt < 2; mt++) {
                const uint32_t am = ka + mt * (16 * ROW_B);
                uint32_t a0 = lds_tf32(am);
                uint32_t a1 = lds_tf32(am + 8 * ROW_B);
                uint32_t a2 = lds_tf32(am + 16);
                uint32_t a3 = lds_tf32(am + 8 * ROW_B + 16);
#pragma unroll
                for (int nt = 0; nt < 4; nt++)
                    mma_tf32(acc[mt][nt][0], acc[mt][nt][1], acc[mt][nt][2], acc[mt][nt][3],
                             a0, a1, a2, a3, bf[nt][0], bf[nt][1]);
            }
        }
        slot = (slot == S_STAGES - 1) ? 0 : slot + 1;
        lslot = (lslot == S_STAGES - 1) ? 0 : lslot + 1;
    }

    // Epilogue: c-frag m16n8: thread holds rows l4, l4+8; cols 2*lm, 2*lm+1
    float* P = g_partial + (size_t)branch * 8192 * 32;
#pragma unroll
    for (int mt = 0; mt < 2; mt++) {
        const int r0 = mtile * M_TILE + w * 32 + mt * 16 + l4;
#pragma unroll
        for (int nt = 0; nt < 4; nt++) {
            const int col = nt * 8 + lm * 2;
            float2* d0 = reinterpret_cast<float2*>(P + (size_t)r0 * 32 + col);
            float2* d1 = reinterpret_cast<float2*>(P + (size_t)(r0 + 8) * 32 + col);
            *d0 = make_float2(acc[mt][nt][0], acc[mt][nt][1]);
            *d1 = make_float2(acc[mt][nt][2], acc[mt][nt][3]);
        }
    }
}

// ============================================================================
// Kernel 3: reduce 4 partials + relu -> out[8192,32] f32
// ============================================================================
__global__ void reduce_relu_kernel(float4* __restrict__ out)
{
    const int i = blockIdx.x * blockDim.x + threadIdx.x;     // 0..65535 float4s
    const float4* p = reinterpret_cast<const float4*>(g_partial);
    float4 a = p[i], b = p[i + 65536], c = p[i + 131072], d = p[i + 196608];
    float4 r;
    r.x = fmaxf(a.x + b.x + c.x + d.x, 0.0f);
    r.y = fmaxf(a.y + b.y + c.y + d.y, 0.0f);
    r.z = fmaxf(a.z + b.z + c.z + d.z, 0.0f);
    r.w = fmaxf(a.w + b.w + c.w + d.w, 0.0f);
    out[i] = r;
}

// ============================================================================
// Launch
// ============================================================================
extern "C" void kernel_launch(void* const* d_in, const int* in_sizes, int n_in,
                              void* d_out, int out_size)
{
    const float* xi  = (const float*)d_in[0];
    const float* xj1 = (const float*)d_in[1];
    const float* xk  = (const float*)d_in[3];
    const float* Gi  = (const float*)d_in[4];
    const float* Ad  = (const float*)d_in[5];
    const float* co  = (const float*)d_in[6];
    const float* Gk  = (const float*)d_in[7];

    cudaFuncSetAttribute(gemm_tf32_kernel,
                         cudaFuncAttributeMaxDynamicSharedMemorySize, SMEM_TOTAL);
    cudaFuncSetAttribute(gemm_tf32_kernel,
                         cudaFuncAttributePreferredSharedMemoryCarveout, 100);

    prep_kernel<<<dim3(64, 4), 256>>>(
        xi, xj1, xk,
        (const float*)d_in[8],  (const float*)d_in[9],
        (const float*)d_in[10], (const float*)d_in[11],
        (const float*)d_in[12], (const float*)d_in[13],
        (const float*)d_in[14], (const float*)d_in[15]);

    gemm_tf32_kernel<<<dim3(32, 4), 256, SMEM_TOTAL>>>(Gi, Ad, co, Gk);

    reduce_relu_kernel<<<256, 256>>>((float4*)d_out);
}

// round 5
// speedup vs baseline: 1.1563x; 1.0966x over previous
#include <cuda_runtime.h>
#include <cstdint>
#include <cstddef>

// ============================================================================
//   z[8192,32] = relu( Gi2j@(xi Wi+bi) + Adj2j@(xj1 Wj1+bj1)
//                    + coAdj2j@(xj1 Wj2+bj2) + Gk2j@(xk Wk+bk) )
// Inputs (metadata order):
//   0 xi, 1 xj1, 2 xj2(unused), 3 xk, 4 Gi2j, 5 Adj2j, 6 coAdj2j, 7 Gk2j,
//   8..11 W_i,W_j1,W_j2,W_k, 12..15 b_i,b_j1,b_j2,b_k
//
// Bench PTX target is plain sm_103 (no 'a' features): no tcgen05/TMEM.
// R5: ldmatrix fragment loads (64 LDS -> 24 LDSM per warp-chunk), drop
// cvt.rna (HW tf32 truncation, CUTLASS-style), 5-stage ring, faster prep.
// ============================================================================

// Scratch (allocation-free: __device__ globals)
__device__ float g_B[4 * 32 * 8192];        // [branch][c][k]  (Y_m^T, k-contiguous)
__device__ float g_partial[4 * 8192 * 32];  // [branch][j][c]

__device__ __forceinline__ uint32_t smem_u32(const void* p) {
    uint32_t a;
    asm("{ .reg .u64 t; cvta.to.shared.u64 t, %1; cvt.u32.u64 %0, t; }" : "=r"(a) : "l"(p));
    return a;
}

#define CP_ASYNC16(dst, src) \
    asm volatile("cp.async.cg.shared.global [%0], [%1], 16;" :: "r"(dst), "l"(src) : "memory")
#define CP_ASYNC16_PF(dst, src) \
    asm volatile("cp.async.cg.shared.global.L2::256B [%0], [%1], 16;" :: "r"(dst), "l"(src) : "memory")
#define CP_COMMIT() asm volatile("cp.async.commit_group;" ::: "memory")
#define CP_WAIT3()  asm volatile("cp.async.wait_group 3;" ::: "memory")

// ldmatrix: b16 view over fp32 data (each b16-pair = one fp32 element).
#define LDSM_X4(r0, r1, r2, r3, addr) \
    asm volatile("ldmatrix.sync.aligned.m8n8.x4.shared.b16 {%0,%1,%2,%3}, [%4];" \
        : "=r"(r0), "=r"(r1), "=r"(r2), "=r"(r3) : "r"(addr))
#define LDSM_X2(r0, r1, addr) \
    asm volatile("ldmatrix.sync.aligned.m8n8.x2.shared.b16 {%0,%1}, [%2];" \
        : "=r"(r0), "=r"(r1) : "r"(addr))

__device__ __forceinline__ void mma_tf32(float& c0, float& c1, float& c2, float& c3,
                                         uint32_t a0, uint32_t a1, uint32_t a2, uint32_t a3,
                                         uint32_t b0, uint32_t b1) {
    asm volatile(
        "mma.sync.aligned.m16n8k8.row.col.f32.tf32.tf32.f32 "
        "{%0,%1,%2,%3}, {%4,%5,%6,%7}, {%8,%9}, {%0,%1,%2,%3};"
        : "+f"(c0), "+f"(c1), "+f"(c2), "+f"(c3)
        : "r"(a0), "r"(a1), "r"(a2), "r"(a3), "r"(b0), "r"(b1));
}

// ============================================================================
// Kernel 1: B prep — g_B[m][c][k] = b_m[c] + sum_t x_m[k,t] * W_m[t,c]
//   grid (256, 4), 256 threads; thread = (cgroup of 4 c's) x (k lane of 32).
// ============================================================================
__global__ void __launch_bounds__(256) prep_kernel(
    const float* __restrict__ xi, const float* __restrict__ xj1, const float* __restrict__ xk,
    const float* __restrict__ Wi, const float* __restrict__ Wj1,
    const float* __restrict__ Wj2, const float* __restrict__ Wk,
    const float* __restrict__ bi, const float* __restrict__ bj1,
    const float* __restrict__ bj2, const float* __restrict__ bk)
{
    const int m = blockIdx.y;
    const float* x = (m == 0) ? xi : (m == 3) ? xk : xj1;  // branch 2 uses xj1 (faithful)
    const float* W = (m == 0) ? Wi : (m == 1) ? Wj1 : (m == 2) ? Wj2 : Wk;
    const float* b = (m == 0) ? bi : (m == 1) ? bj1 : (m == 2) ? bj2 : bk;

    __shared__ float Ws[32][32];
    __shared__ float bs[32];
    const int tid = threadIdx.x;
    for (int i = tid; i < 1024; i += 256) Ws[i >> 5][i & 31] = W[i];
    if (tid < 32) bs[tid] = b[tid];
    __syncthreads();

    const int k = blockIdx.x * 32 + (tid & 31);
    const int c0 = (tid >> 5) * 4;           // 0,4,...,28

    float xr[32];
    const float4* xrow = reinterpret_cast<const float4*>(x + (size_t)k * 32);
#pragma unroll
    for (int t = 0; t < 8; t++) {
        float4 v = xrow[t];
        xr[4 * t] = v.x; xr[4 * t + 1] = v.y; xr[4 * t + 2] = v.z; xr[4 * t + 3] = v.w;
    }
    float acc[4];
#pragma unroll
    for (int c = 0; c < 4; c++) acc[c] = bs[c0 + c];
#pragma unroll
    for (int t = 0; t < 32; t++) {
        const float xv = xr[t];
#pragma unroll
        for (int c = 0; c < 4; c++) acc[c] += xv * Ws[t][c0 + c];
    }
    float* Bout = g_B + (size_t)m * 32 * 8192;
#pragma unroll
    for (int c = 0; c < 4; c++)
        Bout[(size_t)(c0 + c) * 8192 + k] = acc[c];   // 32 consecutive k / warp store
}

// ============================================================================
// Kernel 2: tf32 mma.sync GEMM — partial[m][jtile] = G_m[jtile,:] @ Y_m
//   grid (32, 4), 256 threads (8 warps, warp w owns rows w*32..w*32+31).
//   M_TILE=256, K chunks of 32 floats, 5-stage cp.async ring, wait_group 3.
//   Fragments via ldmatrix (b16 view of fp32); raw fp32 into tf32 MMA.
// ============================================================================
#define M_TILE  256
#define S_STAGES 5
#define T_CHUNKS 256                 // 8192 / 32
#define ROW_B 144                    // 36 floats: rows stride 36 banks == 4 mod 32
#define A_BYTES (M_TILE * ROW_B)     // 36864
#define B_OFF   A_BYTES
#define STAGE_BYTES (A_BYTES + 32 * ROW_B)   // 41472
#define SMEM_TOTAL (S_STAGES * STAGE_BYTES)  // 207360 (202.5 KB; 1 CTA/SM)

__device__ __forceinline__ void load_stage(uint32_t sbase, const float* __restrict__ G,
                                           const float* __restrict__ B, int slot, int kchunk,
                                           int mtile, int tid)
{
    const int kbase = kchunk * 32;
    const uint32_t st = sbase + slot * STAGE_BYTES;
    // A: 256 rows x 8 chunks of 16B (8 consecutive threads -> 128B coalesced)
#pragma unroll
    for (int i = 0; i < 8; i++) {
        int ch = tid + i * 256;              // 0..2047
        int r = ch >> 3, q = ch & 7;
        uint32_t dst = st + r * ROW_B + q * 16;
        const float* src = G + (size_t)(mtile * M_TILE + r) * 8192 + kbase + q * 4;
        CP_ASYNC16_PF(dst, src);             // L2::256B warms next chunk
    }
    // B: 32 rows x 8 chunks of 16B (one op per thread)
    {
        int r = tid >> 3, q = tid & 7;
        uint32_t dst = st + B_OFF + r * ROW_B + q * 16;
        const float* src = B + (size_t)r * 8192 + kbase + q * 4;
        CP_ASYNC16(dst, src);
    }
}

__global__ void __launch_bounds__(256, 1)
gemm_tf32_kernel(const float* __restrict__ G0, const float* __restrict__ G1,
                 const float* __restrict__ G2, const float* __restrict__ G3)
{
    extern __shared__ __align__(128) char smem[];
    const uint32_t sbase = smem_u32(smem);
    const int tid = threadIdx.x;
    const int w = tid >> 5;        // 0..7 (warp owns rows w*32..w*32+31)
    const int lid = tid & 31;
    const int l4 = lid >> 2;       // 0..7
    const int lm = lid & 3;        // 0..3
    const int mtile = blockIdx.x;
    const int branch = blockIdx.y;
    const float* __restrict__ G =
        (branch == 0) ? G0 : (branch == 1) ? G1 : (branch == 2) ? G2 : G3;
    const float* __restrict__ B = g_B + (size_t)branch * 32 * 8192;

    // ldmatrix per-thread row/byte offsets (within a stage):
    //   A x4: tile = lid>>3: {rows +0/+8} x {bytes +0/+16}
    //   B x2: matrix0 (threads 0-7) bytes +0, matrix1 (8-15) bytes +16
    const int lrow8 = lid & 7;
    const uint32_t a_lm_off = (uint32_t)((w * 32 + ((lid >> 3) & 1) * 8 + lrow8) * ROW_B
                                         + ((lid >> 4) & 1) * 16);
    const uint32_t b_lm_off = (uint32_t)(B_OFF + lrow8 * ROW_B + ((lid >> 3) & 1) * 16);

    float acc[2][4][4];            // [mtile16][ntile8][frag]
#pragma unroll
    for (int a = 0; a < 2; a++)
#pragma unroll
        for (int b = 0; b < 4; b++)
#pragma unroll
            for (int c = 0; c < 4; c++) acc[a][b][c] = 0.0f;

    // Prologue: fill stages 0..3 (4 committed groups in flight = 166 KB)
    for (int s = 0; s < S_STAGES - 1; s++) {
        load_stage(sbase, G, B, s, s, mtile, tid);
        CP_COMMIT();
    }

    int slot = 0;                  // = t % 5
    int lslot = S_STAGES - 1;      // = (t+4) % 5
    for (int t = 0; t < T_CHUNKS; t++) {
        CP_WAIT3();                // chunk t complete (3 newer groups may pend)
        __syncthreads();           // all warps done reading slot being refilled

        const int lk = t + S_STAGES - 1;
        if (lk < T_CHUNKS) load_stage(sbase, G, B, lslot, lk, mtile, tid);
        CP_COMMIT();               // commit every iter (possibly empty group)

        const uint32_t st = sbase + slot * STAGE_BYTES;
        const uint32_t a_lm = st + a_lm_off;
        const uint32_t b_lm = st + b_lm_off;

#pragma unroll
        for (int k0 = 0; k0 < 4; k0++) {   // 4 k-steps of 8 (32B per k-step)
            uint32_t bf[4][2];
#pragma unroll
            for (int nt = 0; nt < 4; nt++)
                LDSM_X2(bf[nt][0], bf[nt][1], b_lm + nt * (8 * ROW_B) + k0 * 32);
#pragma unroll
            for (int mt = 0; mt < 2; mt++) {
                uint32_t a0, a1, a2, a3;
                LDSM_X4(a0, a1, a2, a3, a_lm + mt * (16 * ROW_B) + k0 * 32);
#pragma unroll
                for (int nt = 0; nt < 4; nt++)
                    mma_tf32(acc[mt][nt][0], acc[mt][nt][1], acc[mt][nt][2], acc[mt][nt][3],
                             a0, a1, a2, a3, bf[nt][0], bf[nt][1]);
            }
        }
        slot = (slot == S_STAGES - 1) ? 0 : slot + 1;
        lslot = (lslot == S_STAGES - 1) ? 0 : lslot + 1;
    }

    // Epilogue: c-frag m16n8: thread holds rows l4, l4+8; cols 2*lm, 2*lm+1
    float* P = g_partial + (size_t)branch * 8192 * 32;
#pragma unroll
    for (int mt = 0; mt < 2; mt++) {
        const int r0 = mtile * M_TILE + w * 32 + mt * 16 + l4;
#pragma unroll
        for (int nt = 0; nt < 4; nt++) {
            const int col = nt * 8 + lm * 2;
            float2* d0 = reinterpret_cast<float2*>(P + (size_t)r0 * 32 + col);
            float2* d1 = reinterpret_cast<float2*>(P + (size_t)(r0 + 8) * 32 + col);
            *d0 = make_float2(acc[mt][nt][0], acc[mt][nt][1]);
            *d1 = make_float2(acc[mt][nt][2], acc[mt][nt][3]);
        }
    }
}

// ============================================================================
// Kernel 3: reduce 4 partials + relu -> out[8192,32] f32
// ============================================================================
__global__ void reduce_relu_kernel(float4* __restrict__ out)
{
    const int i = blockIdx.x * blockDim.x + threadIdx.x;     // 0..65535 float4s
    const float4* p = reinterpret_cast<const float4*>(g_partial);
    float4 a = p[i], b = p[i + 65536], c = p[i + 131072], d = p[i + 196608];
    float4 r;
    r.x = fmaxf(a.x + b.x + c.x + d.x, 0.0f);
    r.y = fmaxf(a.y + b.y + c.y + d.y, 0.0f);
    r.z = fmaxf(a.z + b.z + c.z + d.z, 0.0f);
    r.w = fmaxf(a.w + b.w + c.w + d.w, 0.0f);
    out[i] = r;
}

// ============================================================================
// Launch
// ============================================================================
extern "C" void kernel_launch(void* const* d_in, const int* in_sizes, int n_in,
                              void* d_out, int out_size)
{
    const float* xi  = (const float*)d_in[0];
    const float* xj1 = (const float*)d_in[1];
    const float* xk  = (const float*)d_in[3];
    const float* Gi  = (const float*)d_in[4];
    const float* Ad  = (const float*)d_in[5];
    const float* co  = (const float*)d_in[6];
    const float* Gk  = (const float*)d_in[7];

    cudaFuncSetAttribute(gemm_tf32_kernel,
                         cudaFuncAttributeMaxDynamicSharedMemorySize, SMEM_TOTAL);
    cudaFuncSetAttribute(gemm_tf32_kernel,
                         cudaFuncAttributePreferredSharedMemoryCarveout, 100);

    prep_kernel<<<dim3(256, 4), 256>>>(
        xi, xj1, xk,
        (const float*)d_in[8],  (const float*)d_in[9],
        (const float*)d_in[10], (const float*)d_in[11],
        (const float*)d_in[12], (const float*)d_in[13],
        (const float*)d_in[14], (const float*)d_in[15]);

    gemm_tf32_kernel<<<dim3(32, 4), 256, SMEM_TOTAL>>>(Gi, Ad, co, Gk);

    reduce_relu_kernel<<<256, 256>>>((float4*)d_out);
}

// round 6
// speedup vs baseline: 1.1574x; 1.0009x over previous
#include <cuda_runtime.h>
#include <cstdint>
#include <cstddef>

// ============================================================================
//   z[8192,32] = relu( Gi2j@(xi Wi+bi) + Adj2j@(xj1 Wj1+bj1)
//                    + coAdj2j@(xj1 Wj2+bj2) + Gk2j@(xk Wk+bk) )
// Inputs (metadata order):
//   0 xi, 1 xj1, 2 xj2(unused), 3 xk, 4 Gi2j, 5 Adj2j, 6 coAdj2j, 7 Gk2j,
//   8..11 W_i,W_j1,W_j2,W_k, 12..15 b_i,b_j1,b_j2,b_k
//
// Bench PTX target is plain sm_103 (no 'a' features): no tcgen05/TMEM.
// R6: prep with coalesced smem staging (+rna-rounded B for error headroom),
// 4 dummy launches so ncu (-s 5) captures the GEMM kernel next round.
// ============================================================================

// Scratch (allocation-free: __device__ globals)
__device__ float g_B[4 * 32 * 8192];        // [branch][c][k]  (Y_m^T, k-contiguous)
__device__ float g_partial[4 * 8192 * 32];  // [branch][j][c]

__device__ __forceinline__ uint32_t smem_u32(const void* p) {
    uint32_t a;
    asm("{ .reg .u64 t; cvta.to.shared.u64 t, %1; cvt.u32.u64 %0, t; }" : "=r"(a) : "l"(p));
    return a;
}

#define CP_ASYNC16(dst, src) \
    asm volatile("cp.async.cg.shared.global [%0], [%1], 16;" :: "r"(dst), "l"(src) : "memory")
#define CP_ASYNC16_PF(dst, src) \
    asm volatile("cp.async.cg.shared.global.L2::256B [%0], [%1], 16;" :: "r"(dst), "l"(src) : "memory")
#define CP_COMMIT() asm volatile("cp.async.commit_group;" ::: "memory")
#define CP_WAIT3()  asm volatile("cp.async.wait_group 3;" ::: "memory")

// ldmatrix: b16 view over fp32 data (each b16-pair = one fp32 element).
#define LDSM_X4(r0, r1, r2, r3, addr) \
    asm volatile("ldmatrix.sync.aligned.m8n8.x4.shared.b16 {%0,%1,%2,%3}, [%4];" \
        : "=r"(r0), "=r"(r1), "=r"(r2), "=r"(r3) : "r"(addr))
#define LDSM_X2(r0, r1, addr) \
    asm volatile("ldmatrix.sync.aligned.m8n8.x2.shared.b16 {%0,%1}, [%2];" \
        : "=r"(r0), "=r"(r1) : "r"(addr))

__device__ __forceinline__ void mma_tf32(float& c0, float& c1, float& c2, float& c3,
                                         uint32_t a0, uint32_t a1, uint32_t a2, uint32_t a3,
                                         uint32_t b0, uint32_t b1) {
    asm volatile(
        "mma.sync.aligned.m16n8k8.row.col.f32.tf32.tf32.f32 "
        "{%0,%1,%2,%3}, {%4,%5,%6,%7}, {%8,%9}, {%0,%1,%2,%3};"
        : "+f"(c0), "+f"(c1), "+f"(c2), "+f"(c3)
        : "r"(a0), "r"(a1), "r"(a2), "r"(a3), "r"(b0), "r"(b1));
}

// ============================================================================
// Kernel 0: dummies (shift ncu's -s 5 capture onto the GEMM launch)
// ============================================================================
__global__ void dummy_kernel() {}

// ============================================================================
// Kernel 1: B prep — g_B[m][c][k] = rna_tf32( b_m[c] + sum_t x_m[k,t] W_m[t,c] )
//   grid (32, 4), 256 threads. Block stages its 256 x-rows through smem with
//   fully-coalesced global loads (fixes the 32x overfetch of earlier versions).
// ============================================================================
__global__ void __launch_bounds__(256) prep_kernel(
    const float* __restrict__ xi, const float* __restrict__ xj1, const float* __restrict__ xk,
    const float* __restrict__ Wi, const float* __restrict__ Wj1,
    const float* __restrict__ Wj2, const float* __restrict__ Wk,
    const float* __restrict__ bi, const float* __restrict__ bj1,
    const float* __restrict__ bj2, const float* __restrict__ bk)
{
    const int m = blockIdx.y;
    const float* x = (m == 0) ? xi : (m == 3) ? xk : xj1;  // branch 2 uses xj1 (faithful)
    const float* W = (m == 0) ? Wi : (m == 1) ? Wj1 : (m == 2) ? Wj2 : Wk;
    const float* b = (m == 0) ? bi : (m == 1) ? bj1 : (m == 2) ? bj2 : bk;

    __shared__ float xs[256][33];    // padded: row reads conflict-free
    __shared__ float Ws[32][32];
    __shared__ float bs[32];
    const int tid = threadIdx.x;
    for (int i = tid; i < 1024; i += 256) Ws[i >> 5][i & 31] = W[i];
    if (tid < 32) bs[tid] = b[tid];

    // Coalesced stage of 256 x-rows (8192 floats)
    const float* xblk = x + (size_t)blockIdx.x * 256 * 32;
#pragma unroll
    for (int i = 0; i < 32; i++) {
        int idx = tid + i * 256;
        xs[idx >> 5][idx & 31] = xblk[idx];
    }
    __syncthreads();

    float xr[32];
#pragma unroll
    for (int t = 0; t < 32; t++) xr[t] = xs[tid][t];

    const int k = blockIdx.x * 256 + tid;
    float* Bout = g_B + (size_t)m * 32 * 8192;
#pragma unroll
    for (int cb = 0; cb < 4; cb++) {         // 4 c-blocks of 8
        float acc[8];
#pragma unroll
        for (int c = 0; c < 8; c++) acc[c] = bs[cb * 8 + c];
#pragma unroll
        for (int t = 0; t < 32; t++) {
            const float xv = xr[t];
#pragma unroll
            for (int c = 0; c < 8; c++) acc[c] += xv * Ws[t][cb * 8 + c];
        }
#pragma unroll
        for (int c = 0; c < 8; c++) {
            uint32_t v = __float_as_uint(acc[c]);
            asm volatile("cvt.rna.tf32.f32 %0, %0;" : "+r"(v));   // pre-round B operand
            Bout[(size_t)(cb * 8 + c) * 8192 + k] = __uint_as_float(v);
        }
    }
}

// ============================================================================
// Kernel 2: tf32 mma.sync GEMM — partial[m][jtile] = G_m[jtile,:] @ Y_m
//   grid (32, 4), 256 threads (8 warps, warp w owns rows w*32..w*32+31).
//   M_TILE=256, K chunks of 32 floats, 5-stage cp.async ring, wait_group 3.
//   Fragments via ldmatrix (b16 view of fp32); raw fp32 A into tf32 MMA.
// ============================================================================
#define M_TILE  256
#define S_STAGES 5
#define T_CHUNKS 256                 // 8192 / 32
#define ROW_B 144                    // 36 floats: rows stride 36 banks == 4 mod 32
#define A_BYTES (M_TILE * ROW_B)     // 36864
#define B_OFF   A_BYTES
#define STAGE_BYTES (A_BYTES + 32 * ROW_B)   // 41472
#define SMEM_TOTAL (S_STAGES * STAGE_BYTES)  // 207360 (202.5 KB; 1 CTA/SM)

__device__ __forceinline__ void load_stage(uint32_t sbase, const float* __restrict__ G,
                                           const float* __restrict__ B, int slot, int kchunk,
                                           int mtile, int tid)
{
    const int kbase = kchunk * 32;
    const uint32_t st = sbase + slot * STAGE_BYTES;
    // A: 256 rows x 8 chunks of 16B (8 consecutive threads -> 128B coalesced)
#pragma unroll
    for (int i = 0; i < 8; i++) {
        int ch = tid + i * 256;              // 0..2047
        int r = ch >> 3, q = ch & 7;
        uint32_t dst = st + r * ROW_B + q * 16;
        const float* src = G + (size_t)(mtile * M_TILE + r) * 8192 + kbase + q * 4;
        CP_ASYNC16_PF(dst, src);             // L2::256B warms next chunk
    }
    // B: 32 rows x 8 chunks of 16B (one op per thread)
    {
        int r = tid >> 3, q = tid & 7;
        uint32_t dst = st + B_OFF + r * ROW_B + q * 16;
        const float* src = B + (size_t)r * 8192 + kbase + q * 4;
        CP_ASYNC16(dst, src);
    }
}

__global__ void __launch_bounds__(256, 1)
gemm_tf32_kernel(const float* __restrict__ G0, const float* __restrict__ G1,
                 const float* __restrict__ G2, const float* __restrict__ G3)
{
    extern __shared__ __align__(128) char smem[];
    const uint32_t sbase = smem_u32(smem);
    const int tid = threadIdx.x;
    const int w = tid >> 5;        // 0..7 (warp owns rows w*32..w*32+31)
    const int lid = tid & 31;
    const int l4 = lid >> 2;       // 0..7
    const int lm = lid & 3;        // 0..3
    const int mtile = blockIdx.x;
    const int branch = blockIdx.y;
    const float* __restrict__ G =
        (branch == 0) ? G0 : (branch == 1) ? G1 : (branch == 2) ? G2 : G3;
    const float* __restrict__ B = g_B + (size_t)branch * 32 * 8192;

    // ldmatrix per-thread row/byte offsets (within a stage):
    //   A x4: tile = lid>>3: {rows +0/+8} x {bytes +0/+16}
    //   B x2: matrix0 (threads 0-7) bytes +0, matrix1 (8-15) bytes +16
    const int lrow8 = lid & 7;
    const uint32_t a_lm_off = (uint32_t)((w * 32 + ((lid >> 3) & 1) * 8 + lrow8) * ROW_B
                                         + ((lid >> 4) & 1) * 16);
    const uint32_t b_lm_off = (uint32_t)(B_OFF + lrow8 * ROW_B + ((lid >> 3) & 1) * 16);

    float acc[2][4][4];            // [mtile16][ntile8][frag]
#pragma unroll
    for (int a = 0; a < 2; a++)
#pragma unroll
        for (int b = 0; b < 4; b++)
#pragma unroll
            for (int c = 0; c < 4; c++) acc[a][b][c] = 0.0f;

    // Prologue: fill stages 0..3 (4 committed groups in flight = 166 KB)
    for (int s = 0; s < S_STAGES - 1; s++) {
        load_stage(sbase, G, B, s, s, mtile, tid);
        CP_COMMIT();
    }

    int slot = 0;                  // = t % 5
    int lslot = S_STAGES - 1;      // = (t+4) % 5
    for (int t = 0; t < T_CHUNKS; t++) {
        CP_WAIT3();                // chunk t complete (3 newer groups may pend)
        __syncthreads();           // all warps done reading slot being refilled

        const int lk = t + S_STAGES - 1;
        if (lk < T_CHUNKS) load_stage(sbase, G, B, lslot, lk, mtile, tid);
        CP_COMMIT();               // commit every iter (possibly empty group)

        const uint32_t st = sbase + slot * STAGE_BYTES;
        const uint32_t a_lm = st + a_lm_off;
        const uint32_t b_lm = st + b_lm_off;

#pragma unroll
        for (int k0 = 0; k0 < 4; k0++) {   // 4 k-steps of 8 (32B per k-step)
            uint32_t bf[4][2];
#pragma unroll
            for (int nt = 0; nt < 4; nt++)
                LDSM_X2(bf[nt][0], bf[nt][1], b_lm + nt * (8 * ROW_B) + k0 * 32);
#pragma unroll
            for (int mt = 0; mt < 2; mt++) {
                uint32_t a0, a1, a2, a3;
                LDSM_X4(a0, a1, a2, a3, a_lm + mt * (16 * ROW_B) + k0 * 32);
#pragma unroll
                for (int nt = 0; nt < 4; nt++)
                    mma_tf32(acc[mt][nt][0], acc[mt][nt][1], acc[mt][nt][2], acc[mt][nt][3],
                             a0, a1, a2, a3, bf[nt][0], bf[nt][1]);
            }
        }
        slot = (slot == S_STAGES - 1) ? 0 : slot + 1;
        lslot = (lslot == S_STAGES - 1) ? 0 : lslot + 1;
    }

    // Epilogue: c-frag m16n8: thread holds rows l4, l4+8; cols 2*lm, 2*lm+1
    float* P = g_partial + (size_t)branch * 8192 * 32;
#pragma unroll
    for (int mt = 0; mt < 2; mt++) {
        const int r0 = mtile * M_TILE + w * 32 + mt * 16 + l4;
#pragma unroll
        for (int nt = 0; nt < 4; nt++) {
            const int col = nt * 8 + lm * 2;
            float2* d0 = reinterpret_cast<float2*>(P + (size_t)r0 * 32 + col);
            float2* d1 = reinterpret_cast<float2*>(P + (size_t)(r0 + 8) * 32 + col);
            *d0 = make_float2(acc[mt][nt][0], acc[mt][nt][1]);
            *d1 = make_float2(acc[mt][nt][2], acc[mt][nt][3]);
        }
    }
}

// ============================================================================
// Kernel 3: reduce 4 partials + relu -> out[8192,32] f32
// ============================================================================
__global__ void reduce_relu_kernel(float4* __restrict__ out)
{
    const int i = blockIdx.x * blockDim.x + threadIdx.x;     // 0..65535 float4s
    const float4* p = reinterpret_cast<const float4*>(g_partial);
    float4 a = p[i], b = p[i + 65536], c = p[i + 131072], d = p[i + 196608];
    float4 r;
    r.x = fmaxf(a.x + b.x + c.x + d.x, 0.0f);
    r.y = fmaxf(a.y + b.y + c.y + d.y, 0.0f);
    r.z = fmaxf(a.z + b.z + c.z + d.z, 0.0f);
    r.w = fmaxf(a.w + b.w + c.w + d.w, 0.0f);
    out[i] = r;
}

// ============================================================================
// Launch
// ============================================================================
extern "C" void kernel_launch(void* const* d_in, const int* in_sizes, int n_in,
                              void* d_out, int out_size)
{
    const float* xi  = (const float*)d_in[0];
    const float* xj1 = (const float*)d_in[1];
    const float* xk  = (const float*)d_in[3];
    const float* Gi  = (const float*)d_in[4];
    const float* Ad  = (const float*)d_in[5];
    const float* co  = (const float*)d_in[6];
    const float* Gk  = (const float*)d_in[7];

    cudaFuncSetAttribute(gemm_tf32_kernel,
                         cudaFuncAttributeMaxDynamicSharedMemorySize, SMEM_TOTAL);
    cudaFuncSetAttribute(gemm_tf32_kernel,
                         cudaFuncAttributePreferredSharedMemoryCarveout, 100);

    // 4 dummies: with 7 launches per call, ncu's "-s 5 -c 1" lands on the GEMM.
    dummy_kernel<<<1, 1>>>();
    dummy_kernel<<<1, 1>>>();
    dummy_kernel<<<1, 1>>>();
    dummy_kernel<<<1, 1>>>();

    prep_kernel<<<dim3(32, 4), 256>>>(
        xi, xj1, xk,
        (const float*)d_in[8],  (const float*)d_in[9],
        (const float*)d_in[10], (const float*)d_in[11],
        (const float*)d_in[12], (const float*)d_in[13],
        (const float*)d_in[14], (const float*)d_in[15]);

    gemm_tf32_kernel<<<dim3(32, 4), 256, SMEM_TOTAL>>>(Gi, Ad, co, Gk);

    reduce_relu_kernel<<<256, 256>>>((float4*)d_out);
}

// round 7
// speedup vs baseline: 1.3708x; 1.1844x over previous
#include <cuda_runtime.h>
#include <cstdint>
#include <cstddef>

// ============================================================================
//   z[8192,32] = relu( Gi2j@(xi Wi+bi) + Adj2j@(xj1 Wj1+bj1)
//                    + coAdj2j@(xj1 Wj2+bj2) + Gk2j@(xk Wk+bk) )
// Inputs (metadata order):
//   0 xi, 1 xj1, 2 xj2(unused), 3 xk, 4 Gi2j, 5 Adj2j, 6 coAdj2j, 7 Gk2j,
//   8..11 W_i,W_j1,W_j2,W_k, 12..15 b_i,b_j1,b_j2,b_k
//
// Bench PTX target is plain sm_103 (no 'a' features): no tcgen05/TMEM.
// R7: dummies removed; GEMM K-chunk 64 with XOR-swizzled 256B rows and a
// 3-stage ring (halves barrier/loop overhead per byte).
// ============================================================================

// Scratch (allocation-free: __device__ globals)
__device__ float g_B[4 * 32 * 8192];        // [branch][c][k]  (Y_m^T, k-contiguous)
__device__ float g_partial[4 * 8192 * 32];  // [branch][j][c]

__device__ __forceinline__ uint32_t smem_u32(const void* p) {
    uint32_t a;
    asm("{ .reg .u64 t; cvta.to.shared.u64 t, %1; cvt.u32.u64 %0, t; }" : "=r"(a) : "l"(p));
    return a;
}

#define CP_ASYNC16(dst, src) \
    asm volatile("cp.async.cg.shared.global [%0], [%1], 16;" :: "r"(dst), "l"(src) : "memory")
#define CP_COMMIT() asm volatile("cp.async.commit_group;" ::: "memory")
#define CP_WAIT1()  asm volatile("cp.async.wait_group 1;" ::: "memory")

// ldmatrix: b16 view over fp32 data (each b16-pair = one fp32 element).
#define LDSM_X4(r0, r1, r2, r3, addr) \
    asm volatile("ldmatrix.sync.aligned.m8n8.x4.shared.b16 {%0,%1,%2,%3}, [%4];" \
        : "=r"(r0), "=r"(r1), "=r"(r2), "=r"(r3) : "r"(addr))
#define LDSM_X2(r0, r1, addr) \
    asm volatile("ldmatrix.sync.aligned.m8n8.x2.shared.b16 {%0,%1}, [%2];" \
        : "=r"(r0), "=r"(r1) : "r"(addr))

__device__ __forceinline__ void mma_tf32(float& c0, float& c1, float& c2, float& c3,
                                         uint32_t a0, uint32_t a1, uint32_t a2, uint32_t a3,
                                         uint32_t b0, uint32_t b1) {
    asm volatile(
        "mma.sync.aligned.m16n8k8.row.col.f32.tf32.tf32.f32 "
        "{%0,%1,%2,%3}, {%4,%5,%6,%7}, {%8,%9}, {%0,%1,%2,%3};"
        : "+f"(c0), "+f"(c1), "+f"(c2), "+f"(c3)
        : "r"(a0), "r"(a1), "r"(a2), "r"(a3), "r"(b0), "r"(b1));
}

// ============================================================================
// Kernel 1: B prep — g_B[m][c][k] = rna_tf32( b_m[c] + sum_t x_m[k,t] W_m[t,c] )
//   grid (32, 4), 256 threads; coalesced smem staging of the 256 x-rows.
// ============================================================================
__global__ void __launch_bounds__(256) prep_kernel(
    const float* __restrict__ xi, const float* __restrict__ xj1, const float* __restrict__ xk,
    const float* __restrict__ Wi, const float* __restrict__ Wj1,
    const float* __restrict__ Wj2, const float* __restrict__ Wk,
    const float* __restrict__ bi, const float* __restrict__ bj1,
    const float* __restrict__ bj2, const float* __restrict__ bk)
{
    const int m = blockIdx.y;
    const float* x = (m == 0) ? xi : (m == 3) ? xk : xj1;  // branch 2 uses xj1 (faithful)
    const float* W = (m == 0) ? Wi : (m == 1) ? Wj1 : (m == 2) ? Wj2 : Wk;
    const float* b = (m == 0) ? bi : (m == 1) ? bj1 : (m == 2) ? bj2 : bk;

    __shared__ float xs[256][33];    // padded: row reads conflict-free
    __shared__ float Ws[32][32];
    __shared__ float bs[32];
    const int tid = threadIdx.x;
    for (int i = tid; i < 1024; i += 256) Ws[i >> 5][i & 31] = W[i];
    if (tid < 32) bs[tid] = b[tid];

    // Coalesced stage of 256 x-rows (8192 floats)
    const float* xblk = x + (size_t)blockIdx.x * 256 * 32;
#pragma unroll
    for (int i = 0; i < 32; i++) {
        int idx = tid + i * 256;
        xs[idx >> 5][idx & 31] = xblk[idx];
    }
    __syncthreads();

    float xr[32];
#pragma unroll
    for (int t = 0; t < 32; t++) xr[t] = xs[tid][t];

    const int k = blockIdx.x * 256 + tid;
    float* Bout = g_B + (size_t)m * 32 * 8192;
#pragma unroll
    for (int cb = 0; cb < 4; cb++) {         // 4 c-blocks of 8
        float acc[8];
#pragma unroll
        for (int c = 0; c < 8; c++) acc[c] = bs[cb * 8 + c];
#pragma unroll
        for (int t = 0; t < 32; t++) {
            const float xv = xr[t];
#pragma unroll
            for (int c = 0; c < 8; c++) acc[c] += xv * Ws[t][cb * 8 + c];
        }
#pragma unroll
        for (int c = 0; c < 8; c++) {
            uint32_t v = __float_as_uint(acc[c]);
            asm volatile("cvt.rna.tf32.f32 %0, %0;" : "+r"(v));   // pre-round B operand
            Bout[(size_t)(cb * 8 + c) * 8192 + k] = __uint_as_float(v);
        }
    }
}

// ============================================================================
// Kernel 2: tf32 mma.sync GEMM — partial[m][jtile] = G_m[jtile,:] @ Y_m
//   grid (32, 4), 256 threads (8 warps, warp w owns rows w*32..w*32+31).
//   M_TILE=256, K chunks of 64 floats (256B rows, XOR-unit swizzle),
//   3-stage cp.async ring, wait_group 1 (2 x 72KB chunks in flight).
//   Swizzle: 16B unit u at row r lives at unit (u ^ (r&7)) -> ldmatrix
//   conflict-free, zero padding. XOR constant per thread = lrow8.
// ============================================================================
#define M_TILE  256
#define S_STAGES 3
#define T_CHUNKS 128                 // 8192 / 64
#define ROW_BYTES 256                // 64 floats, no pad
#define A_BYTES (M_TILE * ROW_BYTES)          // 65536
#define B_OFF   A_BYTES
#define STAGE_BYTES (A_BYTES + 32 * ROW_BYTES)  // 73728
#define SMEM_TOTAL (S_STAGES * STAGE_BYTES)     // 221184 (216 KB; 1 CTA/SM)

__device__ __forceinline__ void load_stage(uint32_t sbase, const float* __restrict__ G,
                                           const float* __restrict__ B, int slot, int kchunk,
                                           int mtile, int tid)
{
    const int kbase = kchunk * 64;
    const uint32_t st = sbase + slot * STAGE_BYTES;
    // A: 256 rows x 16 units of 16B (16 consecutive threads cover a 256B row)
#pragma unroll
    for (int i = 0; i < 16; i++) {
        int ch = tid + i * 256;              // 0..4095
        int r = ch >> 4, u = ch & 15;
        uint32_t dst = st + r * ROW_BYTES + ((u ^ (r & 7)) << 4);
        const float* src = G + (size_t)(mtile * M_TILE + r) * 8192 + kbase + u * 4;
        CP_ASYNC16(dst, src);
    }
    // B: 32 rows x 16 units (2 per thread)
#pragma unroll
    for (int i = 0; i < 2; i++) {
        int ch = tid + i * 256;              // 0..511
        int r = ch >> 4, u = ch & 15;
        uint32_t dst = st + B_OFF + r * ROW_BYTES + ((u ^ (r & 7)) << 4);
        const float* src = B + (size_t)r * 8192 + kbase + u * 4;
        CP_ASYNC16(dst, src);
    }
}

__global__ void __launch_bounds__(256, 1)
gemm_tf32_kernel(const float* __restrict__ G0, const float* __restrict__ G1,
                 const float* __restrict__ G2, const float* __restrict__ G3)
{
    extern __shared__ __align__(256) char smem[];
    const uint32_t sbase = smem_u32(smem);
    const int tid = threadIdx.x;
    const int w = tid >> 5;        // 0..7 (warp owns rows w*32..w*32+31)
    const int lid = tid & 31;
    const int l4 = lid >> 2;       // 0..7
    const int lm = lid & 3;        // 0..3
    const int mtile = blockIdx.x;
    const int branch = blockIdx.y;
    const float* __restrict__ G =
        (branch == 0) ? G0 : (branch == 1) ? G1 : (branch == 2) ? G2 : G3;
    const float* __restrict__ B = g_B + (size_t)branch * 32 * 8192;

    // ldmatrix thread geometry
    const int lrow8 = lid & 7;                   // swizzle XOR for this thread
    const int a_ub  = (lid >> 4) & 1;            // A: unit low bit
    const int b_ub  = (lid >> 3) & 1;            // B: unit low bit
    const uint32_t a_row_off =
        (uint32_t)((w * 32 + ((lid >> 3) & 1) * 8 + lrow8) * ROW_BYTES);
    const uint32_t b_row_off =
        (uint32_t)(B_OFF + lrow8 * ROW_BYTES);

    float acc[2][4][4];            // [mtile16][ntile8][frag]
#pragma unroll
    for (int a = 0; a < 2; a++)
#pragma unroll
        for (int b = 0; b < 4; b++)
#pragma unroll
            for (int c = 0; c < 4; c++) acc[a][b][c] = 0.0f;

    // Prologue: fill stages 0,1 (2 committed groups = 144 KB in flight)
    for (int s = 0; s < S_STAGES - 1; s++) {
        load_stage(sbase, G, B, s, s, mtile, tid);
        CP_COMMIT();
    }

    int slot = 0;                  // = t % 3
    int lslot = S_STAGES - 1;      // = (t+2) % 3
    for (int t = 0; t < T_CHUNKS; t++) {
        CP_WAIT1();                // chunk t complete (1 newer group may pend)
        __syncthreads();           // all warps done with the slot being refilled

        const int lk = t + S_STAGES - 1;
        if (lk < T_CHUNKS) load_stage(sbase, G, B, lslot, lk, mtile, tid);
        CP_COMMIT();               // commit every iter (possibly empty group)

        const uint32_t st = sbase + slot * STAGE_BYTES;
        const uint32_t a_base = st + a_row_off;
        const uint32_t b_base = st + b_row_off;

#pragma unroll
        for (int k0 = 0; k0 < 8; k0++) {   // 8 k-steps of 8 (1 unit pair each)
            const uint32_t au = (uint32_t)(((k0 * 2 + a_ub) ^ lrow8) << 4);
            const uint32_t bu = (uint32_t)(((k0 * 2 + b_ub) ^ lrow8) << 4);
            uint32_t bf[4][2];
#pragma unroll
            for (int nt = 0; nt < 4; nt++)
                LDSM_X2(bf[nt][0], bf[nt][1], b_base + nt * (8 * ROW_BYTES) + bu);
#pragma unroll
            for (int mt = 0; mt < 2; mt++) {
                uint32_t a0, a1, a2, a3;
                LDSM_X4(a0, a1, a2, a3, a_base + mt * (16 * ROW_BYTES) + au);
#pragma unroll
                for (int nt = 0; nt < 4; nt++)
                    mma_tf32(acc[mt][nt][0], acc[mt][nt][1], acc[mt][nt][2], acc[mt][nt][3],
                             a0, a1, a2, a3, bf[nt][0], bf[nt][1]);
            }
        }
        slot = (slot == S_STAGES - 1) ? 0 : slot + 1;
        lslot = (lslot == S_STAGES - 1) ? 0 : lslot + 1;
    }

    // Epilogue: c-frag m16n8: thread holds rows l4, l4+8; cols 2*lm, 2*lm+1
    float* P = g_partial + (size_t)branch * 8192 * 32;
#pragma unroll
    for (int mt = 0; mt < 2; mt++) {
        const int r0 = mtile * M_TILE + w * 32 + mt * 16 + l4;
#pragma unroll
        for (int nt = 0; nt < 4; nt++) {
            const int col = nt * 8 + lm * 2;
            float2* d0 = reinterpret_cast<float2*>(P + (size_t)r0 * 32 + col);
            float2* d1 = reinterpret_cast<float2*>(P + (size_t)(r0 + 8) * 32 + col);
            *d0 = make_float2(acc[mt][nt][0], acc[mt][nt][1]);
            *d1 = make_float2(acc[mt][nt][2], acc[mt][nt][3]);
        }
    }
}

// ============================================================================
// Kernel 3: reduce 4 partials + relu -> out[8192,32] f32
// ============================================================================
__global__ void reduce_relu_kernel(float4* __restrict__ out)
{
    const int i = blockIdx.x * blockDim.x + threadIdx.x;     // 0..65535 float4s
    const float4* p = reinterpret_cast<const float4*>(g_partial);
    float4 a = p[i], b = p[i + 65536], c = p[i + 131072], d = p[i + 196608];
    float4 r;
    r.x = fmaxf(a.x + b.x + c.x + d.x, 0.0f);
    r.y = fmaxf(a.y + b.y + c.y + d.y, 0.0f);
    r.z = fmaxf(a.z + b.z + c.z + d.z, 0.0f);
    r.w = fmaxf(a.w + b.w + c.w + d.w, 0.0f);
    out[i] = r;
}

// ============================================================================
// Launch
// ============================================================================
extern "C" void kernel_launch(void* const* d_in, const int* in_sizes, int n_in,
                              void* d_out, int out_size)
{
    const float* xi  = (const float*)d_in[0];
    const float* xj1 = (const float*)d_in[1];
    const float* xk  = (const float*)d_in[3];
    const float* Gi  = (const float*)d_in[4];
    const float* Ad  = (const float*)d_in[5];
    const float* co  = (const float*)d_in[6];
    const float* Gk  = (const float*)d_in[7];

    cudaFuncSetAttribute(gemm_tf32_kernel,
                         cudaFuncAttributeMaxDynamicSharedMemorySize, SMEM_TOTAL);
    cudaFuncSetAttribute(gemm_tf32_kernel,
                         cudaFuncAttributePreferredSharedMemoryCarveout, 100);

    prep_kernel<<<dim3(32, 4), 256>>>(
        xi, xj1, xk,
        (const float*)d_in[8],  (const float*)d_in[9],
        (const float*)d_in[10], (const float*)d_in[11],
        (const float*)d_in[12], (const float*)d_in[13],
        (const float*)d_in[14], (const float*)d_in[15]);

    gemm_tf32_kernel<<<dim3(32, 4), 256, SMEM_TOTAL>>>(Gi, Ad, co, Gk);

    reduce_relu_kernel<<<256, 256>>>((float4*)d_out);
}